// round 10
// baseline (speedup 1.0000x reference)
#include <cuda_runtime.h>
#include <cuda_fp16.h>

// Fixed shapes
#define BH_ 64
#define S_  8192
#define D_  64
#define M_  64
#define C_  65
#define TS  128
#define NT  8      // tiles per CTA

__device__ float g_buf1[BH_*M_*C_];

__global__ void zero_buf1_kernel() {
    int i = blockIdx.x*blockDim.x + threadIdx.x;
    if (i < BH_*M_*C_) g_buf1[i] = 0.0f;
}

__device__ __forceinline__ unsigned pack_h2(float lo, float hi) {
    __half2 h = __floats2half2_rn(lo, hi);   // x = lo, y = hi
    return *reinterpret_cast<unsigned*>(&h);
}

// m16n8k16 fp16 MMA, fp32 accumulate, D += A*B
__device__ __forceinline__ void mmaf16(float* c, const unsigned* a, const unsigned* b) {
    asm volatile("mma.sync.aligned.m16n8k16.row.col.f32.f16.f16.f32 "
        "{%0,%1,%2,%3}, {%4,%5,%6,%7}, {%8,%9}, {%0,%1,%2,%3};"
        : "+f"(c[0]), "+f"(c[1]), "+f"(c[2]), "+f"(c[3])
        : "r"(a[0]), "r"(a[1]), "r"(a[2]), "r"(a[3]), "r"(b[0]), "r"(b[1]));
}

// Strides (32-bit words)
#define STRH 36   // half2-packed over K-dim: px, qP, sOM, sB1
#define STRT 68   // half2-packed over s: kT, vT
#define STRS 68   // fp32 output staging (pq)

// Phase K word offsets: om 2304 | hr 128 | px 4608 | kT 4352 | vT 4896
#define KOF_OM 0u
#define KOF_HR 2304u
#define KOF_PX 2432u
#define KOF_KT 7040u
#define KOF_VT 11392u
#define PK_WORDS 16288u          // 65152 B -> 3 CTAs/SM

// Phase Q word offsets: om 2304 | hr 128 | px 4608 | qP 4608 | B1 2592
#define QOF_OM 0u
#define QOF_HR 2304u
#define QOF_PX 2432u
#define QOF_QP 7040u
#define QOF_B1 11648u
#define PQ_WORDS 14240u          // 56960 B -> 3 CTAs/SM
// pq staging: fp32 [128][68] overlaid on px+qP (2432 .. 11136 < 11648)

// Load one row (64 fp32) from global, return sum of squares, pack 32 half2.
__device__ __forceinline__ float ld_row_pack(const float* __restrict__ grow, unsigned* pk) {
    const float4* p = (const float4*)grow;
    float ss = 0.f;
#pragma unroll
    for (int j = 0; j < 16; ++j) {
        float4 x = p[j];
        ss += x.x*x.x + x.y*x.y + x.z*x.z + x.w*x.w;
        pk[2*j]   = pack_h2(x.x, x.y);
        pk[2*j+1] = pack_h2(x.z, x.w);
    }
    return ss;
}

// omTh[m][j] = half2{ Om[2j][m], Om[2j+1][m] }  (omega is [d][m] row-major; L2-hot)
__device__ __forceinline__ void setup_om(unsigned* sOM, const float* Og, int tid) {
    for (int i = tid; i < 2048; i += 128) {
        int m = i >> 5, j = i & 31;
        sOM[m*STRH + j] = pack_h2(Og[(2*j)*64 + m], Og[(2*j+1)*64 + m]);
    }
}

// ---------------------------------------------------------------------------
// Phase K: grid (64, 8), 128 threads, 3 CTAs/SM.
// ---------------------------------------------------------------------------
__global__ void __launch_bounds__(128, 3)
pk_kernel(const float* __restrict__ Kg, const float* __restrict__ Vg,
          const float* __restrict__ Og)
{
    extern __shared__ unsigned sm[];
    unsigned* sOM = sm + KOF_OM;
    float*    hr  = (float*)(sm + KOF_HR);
    unsigned* px  = sm + KOF_PX;
    unsigned* kT  = sm + KOF_KT;
    unsigned* vT  = sm + KOF_VT;
    __half*   vh  = (__half*)vT;

    const int tid = threadIdx.x, w = tid >> 5, lane = tid & 31;
    const int gr = lane >> 2, tg = lane & 3;
    const int bh = blockIdx.x, sp = blockIdx.y;

    setup_om(sOM, Og, tid);
    // vT constant rows: c=64 ones, 65..71 zeros
    for (int i = tid; i < 8*STRT; i += 128) {
        int r = i / STRT, jj = i - r*STRT;
        vT[(64 + r)*STRT + jj] = (r == 0) ? 0x3C003C00u : 0u;
    }

    float acc[9][4];
#pragma unroll
    for (int nb = 0; nb < 9; ++nb)
#pragma unroll
        for (int q = 0; q < 4; ++q) acc[nb][q] = 0.f;

    const size_t base0 = ((size_t)bh*S_ + (size_t)(sp*NT)*TS) * D_;

    unsigned ka[32], va[32];
    float kss = ld_row_pack(Kg + base0 + (size_t)tid*D_, ka);
    ld_row_pack(Vg + base0 + (size_t)tid*D_, va);

    for (int t = 0; t < NT; ++t) {
        if (t) __syncthreads();   // prev GEMM1/GEMM2 done with px/kT/vT

        // K row -> px (packed), h -> hr, V row -> vT (16-bit scatter)
        {
            uint4* dst = (uint4*)(px + tid*STRH);
#pragma unroll
            for (int i = 0; i < 8; ++i)
                dst[i] = make_uint4(ka[4*i], ka[4*i+1], ka[4*i+2], ka[4*i+3]);
            hr[tid] = __expf(-0.5f*kss) * 0.125f;
#pragma unroll
            for (int j = 0; j < 16; ++j) {
                __half2 p0 = *(__half2*)&va[2*j];
                __half2 p1 = *(__half2*)&va[2*j+1];
                vh[(4*j+0)*(2*STRT) + tid] = __low2half(p0);
                vh[(4*j+1)*(2*STRT) + tid] = __high2half(p0);
                vh[(4*j+2)*(2*STRT) + tid] = __low2half(p1);
                vh[(4*j+3)*(2*STRT) + tid] = __high2half(p1);
            }
        }
        __syncthreads();

        // GEMM1^T: proj^T[m=64][s=128]; warp w owns s-cols 32w..+31
        float c1[4][4][4];
#pragma unroll
        for (int mb = 0; mb < 4; ++mb)
#pragma unroll
            for (int nb = 0; nb < 4; ++nb)
#pragma unroll
                for (int q = 0; q < 4; ++q) c1[mb][nb][q] = 0.f;

#pragma unroll
        for (int kst = 0; kst < 4; ++kst) {
            unsigned a[4][4];
#pragma unroll
            for (int mb = 0; mb < 4; ++mb) {
                a[mb][0] = sOM[(mb*16+gr)*STRH   + kst*8 + tg];
                a[mb][1] = sOM[(mb*16+gr+8)*STRH + kst*8 + tg];
                a[mb][2] = sOM[(mb*16+gr)*STRH   + kst*8 + 4 + tg];
                a[mb][3] = sOM[(mb*16+gr+8)*STRH + kst*8 + 4 + tg];
            }
#pragma unroll
            for (int nb = 0; nb < 4; ++nb) {
                int s = w*32 + nb*8 + gr;
                unsigned bb[2] = { px[s*STRH + kst*8 + tg],
                                   px[s*STRH + kst*8 + 4 + tg] };
#pragma unroll
                for (int mb = 0; mb < 4; ++mb) mmaf16(c1[mb][nb], a[mb], bb);
            }
        }
        // k' = h*exp: s-pairs -> kT[m][s/2]
#pragma unroll
        for (int nb = 0; nb < 4; ++nb) {
            int s0 = w*32 + nb*8 + 2*tg;
            float h0 = hr[s0], h1 = hr[s0+1];
            int spx = w*16 + nb*4 + tg;
#pragma unroll
            for (int mb = 0; mb < 4; ++mb) {
                int m = mb*16 + gr;
                kT[m*STRT + spx]     = pack_h2(h0*__expf(c1[mb][nb][0]), h1*__expf(c1[mb][nb][1]));
                kT[(m+8)*STRT + spx] = pack_h2(h0*__expf(c1[mb][nb][2]), h1*__expf(c1[mb][nb][3]));
            }
        }
        __syncthreads();

        // Prefetch next tile into registers (overlaps GEMM2)
        if (t + 1 < NT) {
            const size_t noff = base0 + (size_t)(t+1)*TS*D_ + (size_t)tid*D_;
            kss = ld_row_pack(Kg + noff, ka);
            ld_row_pack(Vg + noff, va);
        }

        // GEMM2: acc[m16 of warp][c=72] += k'^T x V over s (8 k16 steps)
#pragma unroll
        for (int kst = 0; kst < 8; ++kst) {
            unsigned a[4];
            a[0] = kT[(w*16+gr)*STRT   + kst*8 + tg];
            a[1] = kT[(w*16+gr+8)*STRT + kst*8 + tg];
            a[2] = kT[(w*16+gr)*STRT   + kst*8 + 4 + tg];
            a[3] = kT[(w*16+gr+8)*STRT + kst*8 + 4 + tg];
#pragma unroll
            for (int nb = 0; nb < 9; ++nb) {
                unsigned bb[2] = { vT[(nb*8+gr)*STRT + kst*8 + tg],
                                   vT[(nb*8+gr)*STRT + kst*8 + 4 + tg] };
                mmaf16(acc[nb], a, bb);
            }
        }
    }

    // Fold into global buf1
    float* b1 = g_buf1 + (size_t)bh*(M_*C_);
    const int m = w*16 + gr;
#pragma unroll
    for (int nb = 0; nb < 9; ++nb) {
        int col = nb*8 + 2*tg;
        if (col < C_) {
            atomicAdd(&b1[m*C_ + col],     acc[nb][0]);
            atomicAdd(&b1[(m+8)*C_ + col], acc[nb][2]);
        }
        if (col + 1 < C_) {
            atomicAdd(&b1[m*C_ + col + 1],     acc[nb][1]);
            atomicAdd(&b1[(m+8)*C_ + col + 1], acc[nb][3]);
        }
    }
}

// ---------------------------------------------------------------------------
// Phase Q: grid (64, 8), 128 threads, 3 CTAs/SM.
// ---------------------------------------------------------------------------
__global__ void __launch_bounds__(128, 3)
pq_kernel(const float* __restrict__ Qg, float* __restrict__ Out,
          const float* __restrict__ Og)
{
    extern __shared__ unsigned sm[];
    unsigned* sOM = sm + QOF_OM;
    float*    hr  = (float*)(sm + QOF_HR);
    unsigned* px  = sm + QOF_PX;
    unsigned* qP  = sm + QOF_QP;
    unsigned* sB1 = sm + QOF_B1;
    float*    stg = (float*)(sm + QOF_PX);   // overlays px+qP after GEMM3

    const int tid = threadIdx.x, w = tid >> 5, lane = tid & 31;
    const int gr = lane >> 2, tg = lane & 3;
    const int bh = blockIdx.x, sp = blockIdx.y;

    setup_om(sOM, Og, tid);
    // B1h[c][j] = half2{ buf1[2j][c], buf1[2j+1][c] }; c>=65 zero
    const float* b1g = g_buf1 + (size_t)bh*(M_*C_);
    for (int i = tid; i < 72*32; i += 128) {
        int c = i >> 5, j = i & 31;
        unsigned v = 0u;
        if (c < C_) v = pack_h2(b1g[(2*j)*C_ + c], b1g[(2*j+1)*C_ + c]);
        sB1[c*STRH + j] = v;
    }

    const size_t base0 = ((size_t)bh*S_ + (size_t)(sp*NT)*TS) * D_;

    unsigned qa[32];
    float qss = ld_row_pack(Qg + base0 + (size_t)tid*D_, qa);

    for (int t = 0; t < NT; ++t) {
        if (t) __syncthreads();   // prev store-out done reading stg region

        {
            uint4* dst = (uint4*)(px + tid*STRH);
#pragma unroll
            for (int i = 0; i < 8; ++i)
                dst[i] = make_uint4(qa[4*i], qa[4*i+1], qa[4*i+2], qa[4*i+3]);
            hr[tid] = __expf(-0.5f*qss) * 0.125f;
        }
        __syncthreads();

        // GEMM1: q'[s=128][m=64]; warp w rows 32w..+31
        {
            float cq[2][8][4];
#pragma unroll
            for (int mb = 0; mb < 2; ++mb)
#pragma unroll
                for (int nb = 0; nb < 8; ++nb)
#pragma unroll
                    for (int q = 0; q < 4; ++q) cq[mb][nb][q] = 0.f;

#pragma unroll
            for (int kst = 0; kst < 4; ++kst) {
                unsigned a[2][4];
#pragma unroll
                for (int mb = 0; mb < 2; ++mb) {
                    int row = w*32 + mb*16 + gr;
                    a[mb][0] = px[row*STRH     + kst*8 + tg];
                    a[mb][1] = px[(row+8)*STRH + kst*8 + tg];
                    a[mb][2] = px[row*STRH     + kst*8 + 4 + tg];
                    a[mb][3] = px[(row+8)*STRH + kst*8 + 4 + tg];
                }
#pragma unroll
                for (int nb = 0; nb < 8; ++nb) {
                    unsigned bb[2] = { sOM[(nb*8+gr)*STRH + kst*8 + tg],
                                       sOM[(nb*8+gr)*STRH + kst*8 + 4 + tg] };
                    mmaf16(cq[0][nb], a[0], bb);
                    mmaf16(cq[1][nb], a[1], bb);
                }
            }
#pragma unroll
            for (int mb = 0; mb < 2; ++mb) {
                int row = w*32 + mb*16 + gr;
                float h0 = hr[row], h8 = hr[row+8];
#pragma unroll
                for (int nb = 0; nb < 8; ++nb) {
                    int mp = nb*4 + tg;
                    qP[row*STRH + mp]     = pack_h2(h0*__expf(cq[mb][nb][0]), h0*__expf(cq[mb][nb][1]));
                    qP[(row+8)*STRH + mp] = pack_h2(h8*__expf(cq[mb][nb][2]), h8*__expf(cq[mb][nb][3]));
                }
            }
        }
        __syncthreads();

        // Prefetch next Q tile (overlaps GEMM3)
        if (t + 1 < NT)
            qss = ld_row_pack(Qg + base0 + (size_t)(t+1)*TS*D_ + (size_t)tid*D_, qa);

        // GEMM3: D[s][c=72] = q' x buf1 over m=64 (4 k16 steps)
        float dq[2][9][4];
#pragma unroll
        for (int mb = 0; mb < 2; ++mb)
#pragma unroll
            for (int nb = 0; nb < 9; ++nb)
#pragma unroll
                for (int q = 0; q < 4; ++q) dq[mb][nb][q] = 0.f;

#pragma unroll
        for (int kst = 0; kst < 4; ++kst) {
            unsigned a[2][4];
#pragma unroll
            for (int mb = 0; mb < 2; ++mb) {
                int row = w*32 + mb*16 + gr;
                a[mb][0] = qP[row*STRH     + kst*8 + tg];
                a[mb][1] = qP[(row+8)*STRH + kst*8 + tg];
                a[mb][2] = qP[row*STRH     + kst*8 + 4 + tg];
                a[mb][3] = qP[(row+8)*STRH + kst*8 + 4 + tg];
            }
#pragma unroll
            for (int nb = 0; nb < 9; ++nb) {
                unsigned bb[2] = { sB1[(nb*8+gr)*STRH + kst*8 + tg],
                                   sB1[(nb*8+gr)*STRH + kst*8 + 4 + tg] };
                mmaf16(dq[0][nb], a[0], bb);
                mmaf16(dq[1][nb], a[1], bb);
            }
        }
        __syncthreads();   // all qP/px reads done; stg overlay now safe

        // divide by denominator (c=64: nb=8 subcol 0), stage fp32
#pragma unroll
        for (int mb = 0; mb < 2; ++mb) {
            int row = w*32 + mb*16 + gr;
            float den0 = __shfl_sync(0xffffffffu, dq[mb][8][0], lane & 28);
            float den8 = __shfl_sync(0xffffffffu, dq[mb][8][2], lane & 28);
            float inv0 = 1.0f / den0, inv8 = 1.0f / den8;
#pragma unroll
            for (int nb = 0; nb < 8; ++nb) {
                int col = nb*8 + 2*tg;
                stg[row*STRS + col]       = dq[mb][nb][0]*inv0;
                stg[row*STRS + col + 1]   = dq[mb][nb][1]*inv0;
                stg[(row+8)*STRS + col]   = dq[mb][nb][2]*inv8;
                stg[(row+8)*STRS + col+1] = dq[mb][nb][3]*inv8;
            }
        }
        __syncthreads();

        // coalesced store 128x64
        float* ob = Out + base0 + (size_t)t*TS*D_;
        for (int i = tid; i < 2048; i += 128) {
            int r = i >> 4, c4 = i & 15;
            float4 v = *(float4*)&stg[r*STRS + 4*c4];
            ((float4*)(ob + (size_t)r*D_))[c4] = v;
        }
    }
}

extern "C" void kernel_launch(void* const* d_in, const int* in_sizes, int n_in,
                              void* d_out, int out_size)
{
    const float* Q  = (const float*)d_in[0];
    const float* K  = (const float*)d_in[1];
    const float* V  = (const float*)d_in[2];
    const float* Om = (const float*)d_in[3];
    float* out = (float*)d_out;
    (void)in_sizes; (void)n_in; (void)out_size;

    const int SMEM_K = PK_WORDS * 4;
    const int SMEM_Q = PQ_WORDS * 4;
    cudaFuncSetAttribute(pk_kernel, cudaFuncAttributeMaxDynamicSharedMemorySize, SMEM_K);
    cudaFuncSetAttribute(pq_kernel, cudaFuncAttributeMaxDynamicSharedMemorySize, SMEM_Q);

    zero_buf1_kernel<<<(BH_*M_*C_ + 255)/256, 256>>>();
    pk_kernel<<<dim3(BH_, S_/(TS*NT)), 128, SMEM_K>>>(K, V, Om);
    pq_kernel<<<dim3(BH_, S_/(TS*NT)), 128, SMEM_Q>>>(Q, out, Om);
}

// round 11
// speedup vs baseline: 1.0679x; 1.0679x over previous
#include <cuda_runtime.h>
#include <cuda_fp16.h>

// Fixed shapes
#define BH_ 64
#define S_  8192
#define D_  64
#define M_  64
#define C_  65
#define TS  128
#define NT  8      // tiles per CTA

__device__ float g_buf1[BH_*M_*C_];

__global__ void zero_buf1_kernel() {
    int i = blockIdx.x*blockDim.x + threadIdx.x;
    if (i < BH_*M_*C_) g_buf1[i] = 0.0f;
}

__device__ __forceinline__ unsigned pack_h2(float lo, float hi) {
    __half2 h = __floats2half2_rn(lo, hi);   // x = lo, y = hi
    return *reinterpret_cast<unsigned*>(&h);
}

// m16n8k16 fp16 MMA, fp32 accumulate, D += A*B
__device__ __forceinline__ void mmaf16(float* c, const unsigned* a, const unsigned* b) {
    asm volatile("mma.sync.aligned.m16n8k16.row.col.f32.f16.f16.f32 "
        "{%0,%1,%2,%3}, {%4,%5,%6,%7}, {%8,%9}, {%0,%1,%2,%3};"
        : "+f"(c[0]), "+f"(c[1]), "+f"(c[2]), "+f"(c[3])
        : "r"(a[0]), "r"(a[1]), "r"(a[2]), "r"(a[3]), "r"(b[0]), "r"(b[1]));
}

// Strides (32-bit words)
#define STRH 36   // half2-packed over K-dim: px, qP, sOM, sB1
#define STRT 68   // half2-packed over s: kT, vT
#define STRS 68   // fp32 output staging (pq)

// Phase K word offsets
#define KOF_OM 0u
#define KOF_HR 2304u
#define KOF_PX 2432u
#define KOF_KT 7040u
#define KOF_VT 11392u
#define PK_WORDS 16288u          // 65152 B; launch_bounds(128,2) -> no spills

// Phase Q word offsets
#define QOF_OM 0u
#define QOF_HR 2304u
#define QOF_PX 2432u
#define QOF_QP 7040u
#define QOF_B1 11648u
#define PQ_WORDS 14240u          // 56960 B -> 3 CTAs/SM
// pq staging: fp32 [128][68] overlaid on px+qP (2432 .. 11136 < 11648)

// Load one row (64 fp32) from global, return sum of squares, pack 32 half2.
__device__ __forceinline__ float ld_row_pack(const float* __restrict__ grow, unsigned* pk) {
    const float4* p = (const float4*)grow;
    float ss = 0.f;
#pragma unroll
    for (int j = 0; j < 16; ++j) {
        float4 x = p[j];
        ss += x.x*x.x + x.y*x.y + x.z*x.z + x.w*x.w;
        pk[2*j]   = pack_h2(x.x, x.y);
        pk[2*j+1] = pack_h2(x.z, x.w);
    }
    return ss;
}

// omTh[m][j] = half2{ Om[2j][m], Om[2j+1][m] }  (omega is [d][m] row-major; L2-hot)
__device__ __forceinline__ void setup_om(unsigned* sOM, const float* Og, int tid) {
    for (int i = tid; i < 2048; i += 128) {
        int m = i >> 5, j = i & 31;
        sOM[m*STRH + j] = pack_h2(Og[(2*j)*64 + m], Og[(2*j+1)*64 + m]);
    }
}

// ---------------------------------------------------------------------------
// Phase K: grid (64, 8), 128 threads, 2 CTAs/SM (spill-free: 255-reg budget).
// ---------------------------------------------------------------------------
__global__ void __launch_bounds__(128, 2)
pk_kernel(const float* __restrict__ Kg, const float* __restrict__ Vg,
          const float* __restrict__ Og)
{
    extern __shared__ unsigned sm[];
    unsigned* sOM = sm + KOF_OM;
    float*    hr  = (float*)(sm + KOF_HR);
    unsigned* px  = sm + KOF_PX;
    unsigned* kT  = sm + KOF_KT;
    unsigned* vT  = sm + KOF_VT;
    __half*   vh  = (__half*)vT;

    const int tid = threadIdx.x, w = tid >> 5, lane = tid & 31;
    const int gr = lane >> 2, tg = lane & 3;
    const int bh = blockIdx.x, sp = blockIdx.y;

    setup_om(sOM, Og, tid);
    // vT constant rows: c=64 ones, 65..71 zeros
    for (int i = tid; i < 8*STRT; i += 128) {
        int r = i / STRT, jj = i - r*STRT;
        vT[(64 + r)*STRT + jj] = (r == 0) ? 0x3C003C00u : 0u;
    }

    float acc[9][4];
#pragma unroll
    for (int nb = 0; nb < 9; ++nb)
#pragma unroll
        for (int q = 0; q < 4; ++q) acc[nb][q] = 0.f;

    const size_t base0 = ((size_t)bh*S_ + (size_t)(sp*NT)*TS) * D_;

    unsigned ka[32], va[32];
    float kss = ld_row_pack(Kg + base0 + (size_t)tid*D_, ka);
    ld_row_pack(Vg + base0 + (size_t)tid*D_, va);

    for (int t = 0; t < NT; ++t) {
        if (t) __syncthreads();   // prev GEMM1/GEMM2 done with px/kT/vT

        // K row -> px (packed), h -> hr, V row -> vT (16-bit scatter)
        {
            uint4* dst = (uint4*)(px + tid*STRH);
#pragma unroll
            for (int i = 0; i < 8; ++i)
                dst[i] = make_uint4(ka[4*i], ka[4*i+1], ka[4*i+2], ka[4*i+3]);
            hr[tid] = __expf(-0.5f*kss) * 0.125f;
#pragma unroll
            for (int j = 0; j < 16; ++j) {
                __half2 p0 = *(__half2*)&va[2*j];
                __half2 p1 = *(__half2*)&va[2*j+1];
                vh[(4*j+0)*(2*STRT) + tid] = __low2half(p0);
                vh[(4*j+1)*(2*STRT) + tid] = __high2half(p0);
                vh[(4*j+2)*(2*STRT) + tid] = __low2half(p1);
                vh[(4*j+3)*(2*STRT) + tid] = __high2half(p1);
            }
        }
        __syncthreads();

        // Prefetch next tile into registers (covered by GEMM1+pack+GEMM2)
        if (t + 1 < NT) {
            const size_t noff = base0 + (size_t)(t+1)*TS*D_ + (size_t)tid*D_;
            kss = ld_row_pack(Kg + noff, ka);
            ld_row_pack(Vg + noff, va);
        }

        // GEMM1^T: proj^T[m=64][s=128]; warp w owns s-cols 32w..+31
        float c1[4][4][4];
#pragma unroll
        for (int mb = 0; mb < 4; ++mb)
#pragma unroll
            for (int nb = 0; nb < 4; ++nb)
#pragma unroll
                for (int q = 0; q < 4; ++q) c1[mb][nb][q] = 0.f;

#pragma unroll
        for (int kst = 0; kst < 4; ++kst) {
            unsigned a[4][4];
#pragma unroll
            for (int mb = 0; mb < 4; ++mb) {
                a[mb][0] = sOM[(mb*16+gr)*STRH   + kst*8 + tg];
                a[mb][1] = sOM[(mb*16+gr+8)*STRH + kst*8 + tg];
                a[mb][2] = sOM[(mb*16+gr)*STRH   + kst*8 + 4 + tg];
                a[mb][3] = sOM[(mb*16+gr+8)*STRH + kst*8 + 4 + tg];
            }
#pragma unroll
            for (int nb = 0; nb < 4; ++nb) {
                int s = w*32 + nb*8 + gr;
                unsigned bb[2] = { px[s*STRH + kst*8 + tg],
                                   px[s*STRH + kst*8 + 4 + tg] };
#pragma unroll
                for (int mb = 0; mb < 4; ++mb) mmaf16(c1[mb][nb], a[mb], bb);
            }
        }
        // k' = h*exp: s-pairs -> kT[m][s/2]
#pragma unroll
        for (int nb = 0; nb < 4; ++nb) {
            int s0 = w*32 + nb*8 + 2*tg;
            float h0 = hr[s0], h1 = hr[s0+1];
            int spx = w*16 + nb*4 + tg;
#pragma unroll
            for (int mb = 0; mb < 4; ++mb) {
                int m = mb*16 + gr;
                kT[m*STRT + spx]     = pack_h2(h0*__expf(c1[mb][nb][0]), h1*__expf(c1[mb][nb][1]));
                kT[(m+8)*STRT + spx] = pack_h2(h0*__expf(c1[mb][nb][2]), h1*__expf(c1[mb][nb][3]));
            }
        }
        __syncthreads();

        // GEMM2: acc[m16 of warp][c=72] += k'^T x V over s (8 k16 steps)
#pragma unroll
        for (int kst = 0; kst < 8; ++kst) {
            unsigned a[4];
            a[0] = kT[(w*16+gr)*STRT   + kst*8 + tg];
            a[1] = kT[(w*16+gr+8)*STRT + kst*8 + tg];
            a[2] = kT[(w*16+gr)*STRT   + kst*8 + 4 + tg];
            a[3] = kT[(w*16+gr+8)*STRT + kst*8 + 4 + tg];
#pragma unroll
            for (int nb = 0; nb < 9; ++nb) {
                unsigned bb[2] = { vT[(nb*8+gr)*STRT + kst*8 + tg],
                                   vT[(nb*8+gr)*STRT + kst*8 + 4 + tg] };
                mmaf16(acc[nb], a, bb);
            }
        }
    }

    // Fold into global buf1
    float* b1 = g_buf1 + (size_t)bh*(M_*C_);
    const int m = w*16 + gr;
#pragma unroll
    for (int nb = 0; nb < 9; ++nb) {
        int col = nb*8 + 2*tg;
        if (col < C_) {
            atomicAdd(&b1[m*C_ + col],     acc[nb][0]);
            atomicAdd(&b1[(m+8)*C_ + col], acc[nb][2]);
        }
        if (col + 1 < C_) {
            atomicAdd(&b1[m*C_ + col + 1],     acc[nb][1]);
            atomicAdd(&b1[(m+8)*C_ + col + 1], acc[nb][3]);
        }
    }
}

// ---------------------------------------------------------------------------
// Phase Q: grid (64, 8), 128 threads, 3 CTAs/SM (live regs ~145 < 170 cap).
// ---------------------------------------------------------------------------
__global__ void __launch_bounds__(128, 3)
pq_kernel(const float* __restrict__ Qg, float* __restrict__ Out,
          const float* __restrict__ Og)
{
    extern __shared__ unsigned sm[];
    unsigned* sOM = sm + QOF_OM;
    float*    hr  = (float*)(sm + QOF_HR);
    unsigned* px  = sm + QOF_PX;
    unsigned* qP  = sm + QOF_QP;
    unsigned* sB1 = sm + QOF_B1;
    float*    stg = (float*)(sm + QOF_PX);   // overlays px+qP after GEMM3

    const int tid = threadIdx.x, w = tid >> 5, lane = tid & 31;
    const int gr = lane >> 2, tg = lane & 3;
    const int bh = blockIdx.x, sp = blockIdx.y;

    setup_om(sOM, Og, tid);
    // B1h[c][j] = half2{ buf1[2j][c], buf1[2j+1][c] }; c>=65 zero
    const float* b1g = g_buf1 + (size_t)bh*(M_*C_);
    for (int i = tid; i < 72*32; i += 128) {
        int c = i >> 5, j = i & 31;
        unsigned v = 0u;
        if (c < C_) v = pack_h2(b1g[(2*j)*C_ + c], b1g[(2*j+1)*C_ + c]);
        sB1[c*STRH + j] = v;
    }

    const size_t base0 = ((size_t)bh*S_ + (size_t)(sp*NT)*TS) * D_;

    unsigned qa[32];
    float qss = ld_row_pack(Qg + base0 + (size_t)tid*D_, qa);

    for (int t = 0; t < NT; ++t) {
        if (t) __syncthreads();   // prev store-out done reading stg region

        {
            uint4* dst = (uint4*)(px + tid*STRH);
#pragma unroll
            for (int i = 0; i < 8; ++i)
                dst[i] = make_uint4(qa[4*i], qa[4*i+1], qa[4*i+2], qa[4*i+3]);
            hr[tid] = __expf(-0.5f*qss) * 0.125f;
        }
        __syncthreads();

        // GEMM1: q'[s=128][m=64]; warp w rows 32w..+31
        {
            float cq[2][8][4];
#pragma unroll
            for (int mb = 0; mb < 2; ++mb)
#pragma unroll
                for (int nb = 0; nb < 8; ++nb)
#pragma unroll
                    for (int q = 0; q < 4; ++q) cq[mb][nb][q] = 0.f;

#pragma unroll
            for (int kst = 0; kst < 4; ++kst) {
                unsigned a[2][4];
#pragma unroll
                for (int mb = 0; mb < 2; ++mb) {
                    int row = w*32 + mb*16 + gr;
                    a[mb][0] = px[row*STRH     + kst*8 + tg];
                    a[mb][1] = px[(row+8)*STRH + kst*8 + tg];
                    a[mb][2] = px[row*STRH     + kst*8 + 4 + tg];
                    a[mb][3] = px[(row+8)*STRH + kst*8 + 4 + tg];
                }
#pragma unroll
                for (int nb = 0; nb < 8; ++nb) {
                    unsigned bb[2] = { sOM[(nb*8+gr)*STRH + kst*8 + tg],
                                       sOM[(nb*8+gr)*STRH + kst*8 + 4 + tg] };
                    mmaf16(cq[0][nb], a[0], bb);
                    mmaf16(cq[1][nb], a[1], bb);
                }
            }
#pragma unroll
            for (int mb = 0; mb < 2; ++mb) {
                int row = w*32 + mb*16 + gr;
                float h0 = hr[row], h8 = hr[row+8];
#pragma unroll
                for (int nb = 0; nb < 8; ++nb) {
                    int mp = nb*4 + tg;
                    qP[row*STRH + mp]     = pack_h2(h0*__expf(cq[mb][nb][0]), h0*__expf(cq[mb][nb][1]));
                    qP[(row+8)*STRH + mp] = pack_h2(h8*__expf(cq[mb][nb][2]), h8*__expf(cq[mb][nb][3]));
                }
            }
        }
        __syncthreads();

        // Prefetch next Q tile (overlaps GEMM3)
        if (t + 1 < NT)
            qss = ld_row_pack(Qg + base0 + (size_t)(t+1)*TS*D_ + (size_t)tid*D_, qa);

        // GEMM3: D[s][c=72] = q' x buf1 over m=64 (4 k16 steps)
        float dq[2][9][4];
#pragma unroll
        for (int mb = 0; mb < 2; ++mb)
#pragma unroll
            for (int nb = 0; nb < 9; ++nb)
#pragma unroll
                for (int q = 0; q < 4; ++q) dq[mb][nb][q] = 0.f;

#pragma unroll
        for (int kst = 0; kst < 4; ++kst) {
            unsigned a[2][4];
#pragma unroll
            for (int mb = 0; mb < 2; ++mb) {
                int row = w*32 + mb*16 + gr;
                a[mb][0] = qP[row*STRH     + kst*8 + tg];
                a[mb][1] = qP[(row+8)*STRH + kst*8 + tg];
                a[mb][2] = qP[row*STRH     + kst*8 + 4 + tg];
                a[mb][3] = qP[(row+8)*STRH + kst*8 + 4 + tg];
            }
#pragma unroll
            for (int nb = 0; nb < 9; ++nb) {
                unsigned bb[2] = { sB1[(nb*8+gr)*STRH + kst*8 + tg],
                                   sB1[(nb*8+gr)*STRH + kst*8 + 4 + tg] };
                mmaf16(dq[0][nb], a[0], bb);
                mmaf16(dq[1][nb], a[1], bb);
            }
        }
        __syncthreads();   // all qP/px reads done; stg overlay now safe

        // divide by denominator (c=64: nb=8 subcol 0), stage fp32
#pragma unroll
        for (int mb = 0; mb < 2; ++mb) {
            int row = w*32 + mb*16 + gr;
            float den0 = __shfl_sync(0xffffffffu, dq[mb][8][0], lane & 28);
            float den8 = __shfl_sync(0xffffffffu, dq[mb][8][2], lane & 28);
            float inv0 = 1.0f / den0, inv8 = 1.0f / den8;
#pragma unroll
            for (int nb = 0; nb < 8; ++nb) {
                int col = nb*8 + 2*tg;
                stg[row*STRS + col]       = dq[mb][nb][0]*inv0;
                stg[row*STRS + col + 1]   = dq[mb][nb][1]*inv0;
                stg[(row+8)*STRS + col]   = dq[mb][nb][2]*inv8;
                stg[(row+8)*STRS + col+1] = dq[mb][nb][3]*inv8;
            }
        }
        __syncthreads();

        // coalesced store 128x64
        float* ob = Out + base0 + (size_t)t*TS*D_;
        for (int i = tid; i < 2048; i += 128) {
            int r = i >> 4, c4 = i & 15;
            float4 v = *(float4*)&stg[r*STRS + 4*c4];
            ((float4*)(ob + (size_t)r*D_))[c4] = v;
        }
    }
}

extern "C" void kernel_launch(void* const* d_in, const int* in_sizes, int n_in,
                              void* d_out, int out_size)
{
    const float* Q  = (const float*)d_in[0];
    const float* K  = (const float*)d_in[1];
    const float* V  = (const float*)d_in[2];
    const float* Om = (const float*)d_in[3];
    float* out = (float*)d_out;
    (void)in_sizes; (void)n_in; (void)out_size;

    const int SMEM_K = PK_WORDS * 4;
    const int SMEM_Q = PQ_WORDS * 4;
    cudaFuncSetAttribute(pk_kernel, cudaFuncAttributeMaxDynamicSharedMemorySize, SMEM_K);
    cudaFuncSetAttribute(pq_kernel, cudaFuncAttributeMaxDynamicSharedMemorySize, SMEM_Q);

    zero_buf1_kernel<<<(BH_*M_*C_ + 255)/256, 256>>>();
    pk_kernel<<<dim3(BH_, S_/(TS*NT)), 128, SMEM_K>>>(K, V, Om);
    pq_kernel<<<dim3(BH_, S_/(TS*NT)), 128, SMEM_Q>>>(Q, out, Om);
}

// round 12
// speedup vs baseline: 1.2351x; 1.1566x over previous
#include <cuda_runtime.h>
#include <cuda_fp16.h>

// Fixed shapes
#define BH_ 64
#define S_  8192
#define D_  64
#define M_  64
#define C_  65
#define TS  128
#define NT  8      // tiles per CTA

__device__ float g_buf1[BH_*M_*C_];

__global__ void zero_buf1_kernel() {
    int i = blockIdx.x*blockDim.x + threadIdx.x;
    if (i < BH_*M_*C_) g_buf1[i] = 0.0f;
}

__device__ __forceinline__ unsigned pack_h2(float lo, float hi) {
    __half2 h = __floats2half2_rn(lo, hi);   // x = lo, y = hi
    return *reinterpret_cast<unsigned*>(&h);
}
__device__ __forceinline__ unsigned smem_u32(const void* p) {
    unsigned a;
    asm("{ .reg .u64 t; cvta.to.shared.u64 t, %1; cvt.u32.u64 %0, t; }" : "=r"(a) : "l"(p));
    return a;
}
__device__ __forceinline__ void cp16(unsigned saddr, const float* g) {
    asm volatile("cp.async.cg.shared.global [%0], [%1], 16;"
                 :: "r"(saddr), "l"(__cvta_generic_to_global(g)));
}
#define CP_COMMIT() asm volatile("cp.async.commit_group;")
#define CP_WAIT1()  asm volatile("cp.async.wait_group 1;")
#define CP_WAIT0()  asm volatile("cp.async.wait_group 0;")

// m16n8k16 fp16 MMA, fp32 accumulate, D += A*B
__device__ __forceinline__ void mmaf16(float* c, const unsigned* a, const unsigned* b) {
    asm volatile("mma.sync.aligned.m16n8k16.row.col.f32.f16.f16.f32 "
        "{%0,%1,%2,%3}, {%4,%5,%6,%7}, {%8,%9}, {%0,%1,%2,%3};"
        : "+f"(c[0]), "+f"(c[1]), "+f"(c[2]), "+f"(c[3])
        : "r"(a[0]), "r"(a[1]), "r"(a[2]), "r"(a[3]), "r"(b[0]), "r"(b[1]));
}

// Strides (32-bit words)
#define STRXK 68  // pk raw fp32 K tiles
#define STRX  72  // pq raw fp32 Q tiles (R9 layout)
#define STRH  36  // half2-packed over K-dim: sOM, qP, sB1
#define STRT  68  // half2-packed over s: kT, vT

// Phase K word offsets (total 28544 words = 114176 B -> 2 CTAs/SM)
#define KOF_OM 0u
#define KOF_HR 2304u
#define KOF_X0 2432u
#define KOF_X1 (KOF_X0 + 128u*STRXK)   // 11136
#define KOF_KT (KOF_X1 + 128u*STRXK)   // 19840  [64][68]
#define KOF_VT (KOF_KT + 64u*STRT)     // 24192  [64][68]
#define PK_WORDS (KOF_VT + 64u*STRT)   // 28544

// Phase Q word offsets (R9 layout; 112256 B -> 2 CTAs/SM)
#define QOF_OM 0u
#define QOF_HR 2304u
#define QOF_X0 2432u
#define QOF_X1 (QOF_X0 + 128u*STRX)    // 11648
#define QOF_QP (QOF_X1 + 128u*STRX)    // 20864  [128][36]
#define QOF_B1 (QOF_QP + 128u*STRH)    // 25472  [72][36]
#define PQ_WORDS (QOF_B1 + 72u*STRH)   // 28064

// One 128x64 fp32 tile, 16 cp.async per thread (128 threads, coalesced)
template<int STRIDE>
__device__ __forceinline__ void issue_tile(const float* g, unsigned sbase, int tid) {
#pragma unroll
    for (int j = 0; j < 16; ++j) {
        int l = j*128 + tid;
        int row = l >> 4, ch = l & 15;
        cp16(sbase + (unsigned)(row*STRIDE + ch*4)*4u, g + row*64 + ch*4);
    }
}

// Load one row (64 fp32), pack 32 half2 (no sumsq).
__device__ __forceinline__ void ld_row_packv(const float* __restrict__ grow, unsigned* pk) {
    const float4* p = (const float4*)grow;
#pragma unroll
    for (int j = 0; j < 16; ++j) {
        float4 x = p[j];
        pk[2*j]   = pack_h2(x.x, x.y);
        pk[2*j+1] = pack_h2(x.z, x.w);
    }
}

// omTh[m][j] = half2{ Om[2j][m], Om[2j+1][m] }
__device__ __forceinline__ void setup_om(unsigned* sOM, const float* Og, int tid) {
    for (int i = tid; i < 2048; i += 128) {
        int m = i >> 5, j = i & 31;
        sOM[m*STRH + j] = pack_h2(Og[(2*j)*64 + m], Og[(2*j+1)*64 + m]);
    }
}

// ---------------------------------------------------------------------------
// Phase K: grid (64, 8), 128 threads, 2 CTAs/SM.
//   K: cp.async double-buffered raw fp32. V: register prefetch -> 16b scatter.
// ---------------------------------------------------------------------------
__global__ void __launch_bounds__(128, 2)
pk_kernel(const float* __restrict__ Kg, const float* __restrict__ Vg,
          const float* __restrict__ Og)
{
    extern __shared__ unsigned sm[];
    unsigned* sOM = sm + KOF_OM;
    float*    hr  = (float*)(sm + KOF_HR);
    float*    sX[2] = { (float*)(sm + KOF_X0), (float*)(sm + KOF_X1) };
    unsigned* kT  = sm + KOF_KT;
    unsigned* vT  = sm + KOF_VT;
    __half*   vh  = (__half*)vT;
    const unsigned xb[2] = { smem_u32(sm + KOF_X0), smem_u32(sm + KOF_X1) };

    const int tid = threadIdx.x, w = tid >> 5, lane = tid & 31;
    const int gr = lane >> 2, tg = lane & 3;
    const int bh = blockIdx.x, sp = blockIdx.y;

    setup_om(sOM, Og, tid);

    float acc[9][4];
#pragma unroll
    for (int nb = 0; nb < 9; ++nb)
#pragma unroll
        for (int q = 0; q < 4; ++q) acc[nb][q] = 0.f;

    // Constant B-fragment for the [1|0..0] column block (c=64..71)
    const unsigned bcn = (gr == 0) ? 0x3C003C00u : 0u;

    const size_t base0 = ((size_t)bh*S_ + (size_t)(sp*NT)*TS) * D_;

    issue_tile<STRXK>(Kg + base0, xb[0], tid);
    CP_COMMIT();
    unsigned va[32];
    ld_row_packv(Vg + base0 + (size_t)tid*D_, va);

    for (int t = 0; t < NT; ++t) {
        const int b = t & 1;
        CP_WAIT0();
        __syncthreads();   // K(t) visible; prev GEMM2 done with vT/kT

        // row prefactor h from raw K tile; V(t) scatter from registers
        {
            const float4* rp = (const float4*)(sX[b] + tid*STRXK);
            float ss = 0.f;
#pragma unroll
            for (int j = 0; j < 16; ++j) {
                float4 x = rp[j];
                ss += x.x*x.x + x.y*x.y + x.z*x.z + x.w*x.w;
            }
            hr[tid] = __expf(-0.5f*ss) * 0.125f;
#pragma unroll
            for (int j = 0; j < 16; ++j) {
                __half2 p0 = *(__half2*)&va[2*j];
                __half2 p1 = *(__half2*)&va[2*j+1];
                vh[(4*j+0)*(2*STRT) + tid] = __low2half(p0);
                vh[(4*j+1)*(2*STRT) + tid] = __high2half(p0);
                vh[(4*j+2)*(2*STRT) + tid] = __low2half(p1);
                vh[(4*j+3)*(2*STRT) + tid] = __high2half(p1);
            }
        }
        __syncthreads();

        // Prefetch tile t+1 (covered by GEMM1+GEMM2)
        if (t + 1 < NT) {
            const size_t noff = base0 + (size_t)(t+1)*TS*D_;
            issue_tile<STRXK>(Kg + noff, xb[b^1], tid);
            CP_COMMIT();
            ld_row_packv(Vg + noff + (size_t)tid*D_, va);
        }

        // GEMM1^T: proj^T[m=64][s=128]; warp w owns s-cols 32w..+31
        float c1[4][4][4];
#pragma unroll
        for (int mb = 0; mb < 4; ++mb)
#pragma unroll
            for (int nb = 0; nb < 4; ++nb)
#pragma unroll
                for (int q = 0; q < 4; ++q) c1[mb][nb][q] = 0.f;

#pragma unroll
        for (int kst = 0; kst < 4; ++kst) {
            unsigned a[4][4];
#pragma unroll
            for (int mb = 0; mb < 4; ++mb) {
                a[mb][0] = sOM[(mb*16+gr)*STRH   + kst*8 + tg];
                a[mb][1] = sOM[(mb*16+gr+8)*STRH + kst*8 + tg];
                a[mb][2] = sOM[(mb*16+gr)*STRH   + kst*8 + 4 + tg];
                a[mb][3] = sOM[(mb*16+gr+8)*STRH + kst*8 + 4 + tg];
            }
#pragma unroll
            for (int nb = 0; nb < 4; ++nb) {
                int s = w*32 + nb*8 + gr;
                float2 x0 = *(const float2*)(sX[b] + s*STRXK + kst*16 + 2*tg);
                float2 x1 = *(const float2*)(sX[b] + s*STRXK + kst*16 + 2*tg + 8);
                unsigned bb[2] = { pack_h2(x0.x, x0.y), pack_h2(x1.x, x1.y) };
#pragma unroll
                for (int mb = 0; mb < 4; ++mb) mmaf16(c1[mb][nb], a[mb], bb);
            }
        }
        // k' = h*exp: s-pairs -> kT[m][s/2]
#pragma unroll
        for (int nb = 0; nb < 4; ++nb) {
            int s0 = w*32 + nb*8 + 2*tg;
            float h0 = hr[s0], h1 = hr[s0+1];
            int spx = w*16 + nb*4 + tg;
#pragma unroll
            for (int mb = 0; mb < 4; ++mb) {
                int m = mb*16 + gr;
                kT[m*STRT + spx]     = pack_h2(h0*__expf(c1[mb][nb][0]), h1*__expf(c1[mb][nb][1]));
                kT[(m+8)*STRT + spx] = pack_h2(h0*__expf(c1[mb][nb][2]), h1*__expf(c1[mb][nb][3]));
            }
        }
        __syncthreads();

        // GEMM2: acc[m16 of warp][c=72] += k'^T x V over s (8 k16 steps)
#pragma unroll
        for (int kst = 0; kst < 8; ++kst) {
            unsigned a[4];
            a[0] = kT[(w*16+gr)*STRT   + kst*8 + tg];
            a[1] = kT[(w*16+gr+8)*STRT + kst*8 + tg];
            a[2] = kT[(w*16+gr)*STRT   + kst*8 + 4 + tg];
            a[3] = kT[(w*16+gr+8)*STRT + kst*8 + 4 + tg];
#pragma unroll
            for (int nb = 0; nb < 8; ++nb) {
                unsigned bb[2] = { vT[(nb*8+gr)*STRT + kst*8 + tg],
                                   vT[(nb*8+gr)*STRT + kst*8 + 4 + tg] };
                mmaf16(acc[nb], a, bb);
            }
            { unsigned bc[2] = { bcn, bcn }; mmaf16(acc[8], a, bc); }
        }
        // no trailing sync: loop-top CP_WAIT0+__syncthreads separates reuse
    }

    // Fold into global buf1
    float* b1 = g_buf1 + (size_t)bh*(M_*C_);
    const int m = w*16 + gr;
#pragma unroll
    for (int nb = 0; nb < 9; ++nb) {
        int col = nb*8 + 2*tg;
        if (col < C_) {
            atomicAdd(&b1[m*C_ + col],     acc[nb][0]);
            atomicAdd(&b1[(m+8)*C_ + col], acc[nb][2]);
        }
        if (col + 1 < C_) {
            atomicAdd(&b1[m*C_ + col + 1],     acc[nb][1]);
            atomicAdd(&b1[(m+8)*C_ + col + 1], acc[nb][3]);
        }
    }
}

// ---------------------------------------------------------------------------
// Phase Q: grid (64, 8), 128 threads — R9 verbatim (cp.async, 2 CTAs/SM).
// ---------------------------------------------------------------------------
__global__ void __launch_bounds__(128)
pq_kernel(const float* __restrict__ Qg, float* __restrict__ Out,
          const float* __restrict__ Og)
{
    extern __shared__ unsigned sm[];
    unsigned* sOM = sm + QOF_OM;
    float*    hr  = (float*)(sm + QOF_HR);
    float*    sX[2] = { (float*)(sm + QOF_X0), (float*)(sm + QOF_X1) };
    unsigned* qP  = sm + QOF_QP;
    unsigned* sB1 = sm + QOF_B1;
    const unsigned xb[2] = { smem_u32(sm + QOF_X0), smem_u32(sm + QOF_X1) };

    const int tid = threadIdx.x, w = tid >> 5, lane = tid & 31;
    const int gr = lane >> 2, tg = lane & 3;
    const int bh = blockIdx.x, sp = blockIdx.y;

    setup_om(sOM, Og, tid);
    const float* b1g = g_buf1 + (size_t)bh*(M_*C_);
    for (int i = tid; i < 72*32; i += 128) {
        int c = i >> 5, j = i & 31;
        unsigned v = 0u;
        if (c < C_) v = pack_h2(b1g[(2*j)*C_ + c], b1g[(2*j+1)*C_ + c]);
        sB1[c*STRH + j] = v;
    }

    const size_t base0 = ((size_t)bh*S_ + (size_t)(sp*NT)*TS) * D_;
    issue_tile<STRX>(Qg + base0, xb[0], tid);
    CP_COMMIT();

    for (int t = 0; t < NT; ++t) {
        const int b = t & 1;
        if (t + 1 < NT) {
            issue_tile<STRX>(Qg + base0 + (size_t)(t+1)*TS*D_, xb[b^1], tid);
            CP_COMMIT();
            CP_WAIT1();
        } else {
            CP_WAIT0();
        }
        __syncthreads();

        {
            const float4* rp = (const float4*)(sX[b] + tid*STRX);
            float ss = 0.f;
#pragma unroll
            for (int j = 0; j < 16; ++j) {
                float4 x = rp[j];
                ss += x.x*x.x + x.y*x.y + x.z*x.z + x.w*x.w;
            }
            hr[tid] = __expf(-0.5f*ss) * 0.125f;
        }
        __syncthreads();

        // GEMM1: q'[s=128][m=64]; warp w rows 32w..+31
        {
            float cq[2][8][4];
#pragma unroll
            for (int mb = 0; mb < 2; ++mb)
#pragma unroll
                for (int nb = 0; nb < 8; ++nb)
#pragma unroll
                    for (int q = 0; q < 4; ++q) cq[mb][nb][q] = 0.f;

#pragma unroll
            for (int kst = 0; kst < 4; ++kst) {
                unsigned a[2][4];
#pragma unroll
                for (int mb = 0; mb < 2; ++mb) {
                    int row = w*32 + mb*16 + gr;
                    float2 p0 = *(const float2*)(sX[b] + row*STRX     + kst*16 + 2*tg);
                    float2 p1 = *(const float2*)(sX[b] + (row+8)*STRX + kst*16 + 2*tg);
                    float2 p2 = *(const float2*)(sX[b] + row*STRX     + kst*16 + 2*tg + 8);
                    float2 p3 = *(const float2*)(sX[b] + (row+8)*STRX + kst*16 + 2*tg + 8);
                    a[mb][0] = pack_h2(p0.x, p0.y);
                    a[mb][1] = pack_h2(p1.x, p1.y);
                    a[mb][2] = pack_h2(p2.x, p2.y);
                    a[mb][3] = pack_h2(p3.x, p3.y);
                }
#pragma unroll
                for (int nb = 0; nb < 8; ++nb) {
                    unsigned bb[2] = { sOM[(nb*8+gr)*STRH + kst*8 + tg],
                                       sOM[(nb*8+gr)*STRH + kst*8 + 4 + tg] };
                    mmaf16(cq[0][nb], a[0], bb);
                    mmaf16(cq[1][nb], a[1], bb);
                }
            }
#pragma unroll
            for (int mb = 0; mb < 2; ++mb) {
                int row = w*32 + mb*16 + gr;
                float h0 = hr[row], h8 = hr[row+8];
#pragma unroll
                for (int nb = 0; nb < 8; ++nb) {
                    int mp = nb*4 + tg;
                    qP[row*STRH + mp]     = pack_h2(h0*__expf(cq[mb][nb][0]), h0*__expf(cq[mb][nb][1]));
                    qP[(row+8)*STRH + mp] = pack_h2(h8*__expf(cq[mb][nb][2]), h8*__expf(cq[mb][nb][3]));
                }
            }
        }
        __syncthreads();

        // GEMM3: D[s][c=72] = q' x buf1 over m=64 (4 k16 steps)
        float dq[2][9][4];
#pragma unroll
        for (int mb = 0; mb < 2; ++mb)
#pragma unroll
            for (int nb = 0; nb < 9; ++nb)
#pragma unroll
                for (int q = 0; q < 4; ++q) dq[mb][nb][q] = 0.f;

#pragma unroll
        for (int kst = 0; kst < 4; ++kst) {
            unsigned a[2][4];
#pragma unroll
            for (int mb = 0; mb < 2; ++mb) {
                int row = w*32 + mb*16 + gr;
                a[mb][0] = qP[row*STRH     + kst*8 + tg];
                a[mb][1] = qP[(row+8)*STRH + kst*8 + tg];
                a[mb][2] = qP[row*STRH     + kst*8 + 4 + tg];
                a[mb][3] = qP[(row+8)*STRH + kst*8 + 4 + tg];
            }
#pragma unroll
            for (int nb = 0; nb < 9; ++nb) {
                unsigned bb[2] = { sB1[(nb*8+gr)*STRH + kst*8 + tg],
                                   sB1[(nb*8+gr)*STRH + kst*8 + 4 + tg] };
                mmaf16(dq[0][nb], a[0], bb);
                mmaf16(dq[1][nb], a[1], bb);
            }
        }

        // divide by denominator, stage into free X buffer (current b)
        float* stg = sX[b];
#pragma unroll
        for (int mb = 0; mb < 2; ++mb) {
            int row = w*32 + mb*16 + gr;
            float den0 = __shfl_sync(0xffffffffu, dq[mb][8][0], lane & 28);
            float den8 = __shfl_sync(0xffffffffu, dq[mb][8][2], lane & 28);
            float inv0 = 1.0f / den0, inv8 = 1.0f / den8;
#pragma unroll
            for (int nb = 0; nb < 8; ++nb) {
                int col = nb*8 + 2*tg;
                stg[row*STRX + col]       = dq[mb][nb][0]*inv0;
                stg[row*STRX + col + 1]   = dq[mb][nb][1]*inv0;
                stg[(row+8)*STRX + col]   = dq[mb][nb][2]*inv8;
                stg[(row+8)*STRX + col+1] = dq[mb][nb][3]*inv8;
            }
        }
        __syncthreads();

        // coalesced store 128x64
        float* ob = Out + base0 + (size_t)t*TS*D_;
        for (int i = tid; i < 2048; i += 128) {
            int r = i >> 4, c4 = i & 15;
            float4 v = *(float4*)&stg[r*STRX + 4*c4];
            ((float4*)(ob + (size_t)r*D_))[c4] = v;
        }
        __syncthreads();   // stg reused as cp.async dst two tiles later
    }
}

extern "C" void kernel_launch(void* const* d_in, const int* in_sizes, int n_in,
                              void* d_out, int out_size)
{
    const float* Q  = (const float*)d_in[0];
    const float* K  = (const float*)d_in[1];
    const float* V  = (const float*)d_in[2];
    const float* Om = (const float*)d_in[3];
    float* out = (float*)d_out;
    (void)in_sizes; (void)n_in; (void)out_size;

    const int SMEM_K = PK_WORDS * 4;
    const int SMEM_Q = PQ_WORDS * 4;
    cudaFuncSetAttribute(pk_kernel, cudaFuncAttributeMaxDynamicSharedMemorySize, SMEM_K);
    cudaFuncSetAttribute(pq_kernel, cudaFuncAttributeMaxDynamicSharedMemorySize, SMEM_Q);

    zero_buf1_kernel<<<(BH_*M_*C_ + 255)/256, 256>>>();
    pk_kernel<<<dim3(BH_, S_/(TS*NT)), 128, SMEM_K>>>(K, V, Om);
    pq_kernel<<<dim3(BH_, S_/(TS*NT)), 128, SMEM_Q>>>(Q, out, Om);
}

// round 13
// speedup vs baseline: 1.2779x; 1.0347x over previous
#include <cuda_runtime.h>
#include <cuda_fp16.h>

// Fixed shapes
#define BH_ 64
#define S_  8192
#define D_  64
#define M_  64
#define C_  65
#define TS  128
#define NT  8      // tiles per CTA

__device__ float g_buf1[BH_*M_*C_];

__global__ void zero_buf1_kernel() {
    int i = blockIdx.x*blockDim.x + threadIdx.x;
    if (i < BH_*M_*C_) g_buf1[i] = 0.0f;
}

__device__ __forceinline__ unsigned pack_h2(float lo, float hi) {
    __half2 h = __floats2half2_rn(lo, hi);   // x = lo, y = hi
    return *reinterpret_cast<unsigned*>(&h);
}
__device__ __forceinline__ unsigned smem_u32(const void* p) {
    unsigned a;
    asm("{ .reg .u64 t; cvta.to.shared.u64 t, %1; cvt.u32.u64 %0, t; }" : "=r"(a) : "l"(p));
    return a;
}
__device__ __forceinline__ void cp16(unsigned saddr, const float* g) {
    asm volatile("cp.async.cg.shared.global [%0], [%1], 16;"
                 :: "r"(saddr), "l"(__cvta_generic_to_global(g)));
}
#define CP_COMMIT() asm volatile("cp.async.commit_group;")
#define CP_WAIT1()  asm volatile("cp.async.wait_group 1;")
#define CP_WAIT0()  asm volatile("cp.async.wait_group 0;")

// m16n8k16 fp16 MMA, fp32 accumulate, D += A*B
__device__ __forceinline__ void mmaf16(float* c, const unsigned* a, const unsigned* b) {
    asm volatile("mma.sync.aligned.m16n8k16.row.col.f32.f16.f16.f32 "
        "{%0,%1,%2,%3}, {%4,%5,%6,%7}, {%8,%9}, {%0,%1,%2,%3};"
        : "+f"(c[0]), "+f"(c[1]), "+f"(c[2]), "+f"(c[3])
        : "r"(a[0]), "r"(a[1]), "r"(a[2]), "r"(a[3]), "r"(b[0]), "r"(b[1]));
}

// Strides (32-bit words)
#define STRX 72   // raw fp32 tiles (K/V/Q)
#define STRO 36   // half2-packed over K-dim: sOM, qP, sB1
#define STRT 68   // half2-packed over s: kT, vT

// Phase K word offsets (R9 layout, vT shrunk to 64 rows)
#define KOF_OM 0u
#define KOF_HR 2304u
#define KOF_X0 2432u
#define KOF_X1 (KOF_X0 + 128u*STRX)
#define KOF_V0 (KOF_X1 + 128u*STRX)
#define KOF_V1 (KOF_V0 + 128u*STRX)
#define KOF_KT (KOF_V1 + 128u*STRX)          // [64][68]
#define KOF_VT (KOF_KT + 64u*STRT)           // [64][68]
#define PK_WORDS (KOF_VT + 64u*STRT)         // 48000 words = 192000 B (1 CTA/SM)

// Phase Q word offsets (R9 layout; 112256 B -> 2 CTAs/SM)
#define QOF_OM 0u
#define QOF_HR 2304u
#define QOF_X0 2432u
#define QOF_X1 (QOF_X0 + 128u*STRX)
#define QOF_QP (QOF_X1 + 128u*STRX)          // [128][36]
#define QOF_B1 (QOF_QP + 128u*STRO)          // [72][36]
#define PQ_WORDS (QOF_B1 + 72u*STRO)

// One 128x64 fp32 tile, 16 cp.async per thread (128 threads, coalesced)
__device__ __forceinline__ void issue_tile(const float* g, unsigned sbase, int tid) {
#pragma unroll
    for (int j = 0; j < 16; ++j) {
        int l = j*128 + tid;
        int row = l >> 4, ch = l & 15;
        cp16(sbase + (unsigned)(row*STRX + ch*4)*4u, g + row*64 + ch*4);
    }
}

// omTh[m][j] = half2{ Om[2j][m], Om[2j+1][m] }  (omega is [d][m] row-major)
__device__ __forceinline__ void setup_om(unsigned* sOM, const float* Og, int tid) {
    for (int i = tid; i < 2048; i += 128) {
        int m = i >> 5, j = i & 31;
        sOM[m*STRO + j] = pack_h2(Og[(2*j)*64 + m], Og[(2*j+1)*64 + m]);
    }
}

// ---------------------------------------------------------------------------
// Phase K: grid (64, 8), 128 threads, cp.async double-buffered (R9 skeleton).
// Delta vs R9: omega A-fragments hoisted to registers; GEMM2's ones-column
// block uses a constant fragment (vT padding rows deleted).
// ---------------------------------------------------------------------------
__global__ void __launch_bounds__(128)
pk_kernel(const float* __restrict__ Kg, const float* __restrict__ Vg,
          const float* __restrict__ Og)
{
    extern __shared__ unsigned sm[];
    unsigned* sOM = sm + KOF_OM;
    float*    hr  = (float*)(sm + KOF_HR);
    float*    sX[2] = { (float*)(sm + KOF_X0), (float*)(sm + KOF_X1) };
    float*    sV[2] = { (float*)(sm + KOF_V0), (float*)(sm + KOF_V1) };
    unsigned* kT = sm + KOF_KT;
    unsigned* vT = sm + KOF_VT;
    const unsigned xb[2] = { smem_u32(sm + KOF_X0), smem_u32(sm + KOF_X1) };
    const unsigned vb[2] = { smem_u32(sm + KOF_V0), smem_u32(sm + KOF_V1) };

    const int tid = threadIdx.x, w = tid >> 5, lane = tid & 31;
    const int gr = lane >> 2, tg = lane & 3;
    const int bh = blockIdx.x, sp = blockIdx.y;

    setup_om(sOM, Og, tid);

    float acc[9][4];
#pragma unroll
    for (int nb = 0; nb < 9; ++nb)
#pragma unroll
        for (int q = 0; q < 4; ++q) acc[nb][q] = 0.f;

    // Constant B-fragment for the [1|0..0] block (c=64..71)
    const unsigned bcn = (gr == 0) ? 0x3C003C00u : 0u;

    const size_t base0 = ((size_t)bh*S_ + (size_t)(sp*NT)*TS) * D_;
    issue_tile(Kg + base0, xb[0], tid);
    issue_tile(Vg + base0, vb[0], tid);
    CP_COMMIT();

    __syncthreads();  // sOM visible block-wide

    // Hoist omega A-fragments (loop-invariant): omr[kst][mb][q], 64 regs
    unsigned omr[4][4][4];
#pragma unroll
    for (int kst = 0; kst < 4; ++kst)
#pragma unroll
        for (int mb = 0; mb < 4; ++mb) {
            omr[kst][mb][0] = sOM[(mb*16+gr)*STRO   + kst*8 + tg];
            omr[kst][mb][1] = sOM[(mb*16+gr+8)*STRO + kst*8 + tg];
            omr[kst][mb][2] = sOM[(mb*16+gr)*STRO   + kst*8 + 4 + tg];
            omr[kst][mb][3] = sOM[(mb*16+gr+8)*STRO + kst*8 + 4 + tg];
        }

    for (int t = 0; t < NT; ++t) {
        const int b = t & 1;
        if (t + 1 < NT) {
            const size_t noff = base0 + (size_t)(t+1)*TS*D_;
            issue_tile(Kg + noff, xb[b^1], tid);
            issue_tile(Vg + noff, vb[b^1], tid);
            CP_COMMIT();
            CP_WAIT1();
        } else {
            CP_WAIT0();
        }
        __syncthreads();

        // row prefactor h (thread = row); V^T 16-bit scatter from raw V
        {
            const float4* rp = (const float4*)(sX[b] + tid*STRX);
            float ss = 0.f;
#pragma unroll
            for (int j = 0; j < 16; ++j) {
                float4 x = rp[j];
                ss += x.x*x.x + x.y*x.y + x.z*x.z + x.w*x.w;
            }
            hr[tid] = __expf(-0.5f*ss) * 0.125f;

            const float4* vp = (const float4*)(sV[b] + tid*STRX);
            __half* vh = (__half*)vT;
#pragma unroll
            for (int j = 0; j < 16; ++j) {
                float4 v = vp[j];
                vh[(4*j+0)*(2*STRT) + tid] = __float2half_rn(v.x);
                vh[(4*j+1)*(2*STRT) + tid] = __float2half_rn(v.y);
                vh[(4*j+2)*(2*STRT) + tid] = __float2half_rn(v.z);
                vh[(4*j+3)*(2*STRT) + tid] = __float2half_rn(v.w);
            }
        }
        __syncthreads();

        // GEMM1^T: proj^T[m=64][s=128]; warp w owns s-cols 32w..+31
        float c1[4][4][4];
#pragma unroll
        for (int mb = 0; mb < 4; ++mb)
#pragma unroll
            for (int nb = 0; nb < 4; ++nb)
#pragma unroll
                for (int q = 0; q < 4; ++q) c1[mb][nb][q] = 0.f;

#pragma unroll
        for (int kst = 0; kst < 4; ++kst) {
#pragma unroll
            for (int nb = 0; nb < 4; ++nb) {
                int s = w*32 + nb*8 + gr;
                float2 x0 = *(const float2*)(sX[b] + s*STRX + kst*16 + 2*tg);
                float2 x1 = *(const float2*)(sX[b] + s*STRX + kst*16 + 2*tg + 8);
                unsigned bb[2] = { pack_h2(x0.x, x0.y), pack_h2(x1.x, x1.y) };
#pragma unroll
                for (int mb = 0; mb < 4; ++mb) mmaf16(c1[mb][nb], omr[kst][mb], bb);
            }
        }
        // k' = h*exp: s-pairs -> kT[m][s/2]
#pragma unroll
        for (int nb = 0; nb < 4; ++nb) {
            int s0 = w*32 + nb*8 + 2*tg;
            float h0 = hr[s0], h1 = hr[s0+1];
            int spx = w*16 + nb*4 + tg;
#pragma unroll
            for (int mb = 0; mb < 4; ++mb) {
                int m = mb*16 + gr;
                kT[m*STRT + spx]     = pack_h2(h0*__expf(c1[mb][nb][0]), h1*__expf(c1[mb][nb][1]));
                kT[(m+8)*STRT + spx] = pack_h2(h0*__expf(c1[mb][nb][2]), h1*__expf(c1[mb][nb][3]));
            }
        }
        __syncthreads();

        // GEMM2: acc[m16 of warp][c=72] += k'^T x V over s (8 k16 steps)
#pragma unroll
        for (int kst = 0; kst < 8; ++kst) {
            unsigned a[4];
            a[0] = kT[(w*16+gr)*STRT   + kst*8 + tg];
            a[1] = kT[(w*16+gr+8)*STRT + kst*8 + tg];
            a[2] = kT[(w*16+gr)*STRT   + kst*8 + 4 + tg];
            a[3] = kT[(w*16+gr+8)*STRT + kst*8 + 4 + tg];
#pragma unroll
            for (int nb = 0; nb < 8; ++nb) {
                unsigned bb[2] = { vT[(nb*8+gr)*STRT + kst*8 + tg],
                                   vT[(nb*8+gr)*STRT + kst*8 + 4 + tg] };
                mmaf16(acc[nb], a, bb);
            }
            { unsigned bc[2] = { bcn, bcn }; mmaf16(acc[8], a, bc); }
        }
        __syncthreads();   // kT / vT reused next tile
    }

    // Fold into global buf1
    float* b1 = g_buf1 + (size_t)bh*(M_*C_);
    const int m = w*16 + gr;
#pragma unroll
    for (int nb = 0; nb < 9; ++nb) {
        int col = nb*8 + 2*tg;
        if (col < C_) {
            atomicAdd(&b1[m*C_ + col],     acc[nb][0]);
            atomicAdd(&b1[(m+8)*C_ + col], acc[nb][2]);
        }
        if (col + 1 < C_) {
            atomicAdd(&b1[m*C_ + col + 1],     acc[nb][1]);
            atomicAdd(&b1[(m+8)*C_ + col + 1], acc[nb][3]);
        }
    }
}

// ---------------------------------------------------------------------------
// Phase Q: grid (64, 8), 128 threads, 2 CTAs/SM (R9 skeleton).
// Delta vs R9: buf1 B-fragments for GEMM3 hoisted to registers (72 regs).
// ---------------------------------------------------------------------------
__global__ void __launch_bounds__(128)
pq_kernel(const float* __restrict__ Qg, float* __restrict__ Out,
          const float* __restrict__ Og)
{
    extern __shared__ unsigned sm[];
    unsigned* sOM = sm + QOF_OM;
    float*    hr  = (float*)(sm + QOF_HR);
    float*    sX[2] = { (float*)(sm + QOF_X0), (float*)(sm + QOF_X1) };
    unsigned* qP = sm + QOF_QP;
    unsigned* sB1 = sm + QOF_B1;
    const unsigned xb[2] = { smem_u32(sm + QOF_X0), smem_u32(sm + QOF_X1) };

    const int tid = threadIdx.x, w = tid >> 5, lane = tid & 31;
    const int gr = lane >> 2, tg = lane & 3;
    const int bh = blockIdx.x, sp = blockIdx.y;

    setup_om(sOM, Og, tid);
    // B1h[c][j] = half2{ buf1[2j][c], buf1[2j+1][c] }; c>=65 zero
    const float* b1g = g_buf1 + (size_t)bh*(M_*C_);
    for (int i = tid; i < 72*32; i += 128) {
        int c = i >> 5, j = i & 31;
        unsigned v = 0u;
        if (c < C_) v = pack_h2(b1g[(2*j)*C_ + c], b1g[(2*j+1)*C_ + c]);
        sB1[c*STRO + j] = v;
    }

    const size_t base0 = ((size_t)bh*S_ + (size_t)(sp*NT)*TS) * D_;
    issue_tile(Qg + base0, xb[0], tid);
    CP_COMMIT();

    __syncthreads();  // sB1 visible block-wide

    // Hoist buf1 B-fragments (loop-invariant): b1r[kst][nb][2], 72 regs
    unsigned b1r[4][9][2];
#pragma unroll
    for (int kst = 0; kst < 4; ++kst)
#pragma unroll
        for (int nb = 0; nb < 9; ++nb) {
            b1r[kst][nb][0] = sB1[(nb*8+gr)*STRO + kst*8 + tg];
            b1r[kst][nb][1] = sB1[(nb*8+gr)*STRO + kst*8 + 4 + tg];
        }

    for (int t = 0; t < NT; ++t) {
        const int b = t & 1;
        if (t + 1 < NT) {
            issue_tile(Qg + base0 + (size_t)(t+1)*TS*D_, xb[b^1], tid);
            CP_COMMIT();
            CP_WAIT1();
        } else {
            CP_WAIT0();
        }
        __syncthreads();

        {
            const float4* rp = (const float4*)(sX[b] + tid*STRX);
            float ss = 0.f;
#pragma unroll
            for (int j = 0; j < 16; ++j) {
                float4 x = rp[j];
                ss += x.x*x.x + x.y*x.y + x.z*x.z + x.w*x.w;
            }
            hr[tid] = __expf(-0.5f*ss) * 0.125f;
        }
        __syncthreads();

        // GEMM1: q'[s=128][m=64]; warp w rows 32w..+31
        {
            float cq[2][8][4];
#pragma unroll
            for (int mb = 0; mb < 2; ++mb)
#pragma unroll
                for (int nb = 0; nb < 8; ++nb)
#pragma unroll
                    for (int q = 0; q < 4; ++q) cq[mb][nb][q] = 0.f;

#pragma unroll
            for (int kst = 0; kst < 4; ++kst) {
                unsigned a[2][4];
#pragma unroll
                for (int mb = 0; mb < 2; ++mb) {
                    int row = w*32 + mb*16 + gr;
                    float2 p0 = *(const float2*)(sX[b] + row*STRX     + kst*16 + 2*tg);
                    float2 p1 = *(const float2*)(sX[b] + (row+8)*STRX + kst*16 + 2*tg);
                    float2 p2 = *(const float2*)(sX[b] + row*STRX     + kst*16 + 2*tg + 8);
                    float2 p3 = *(const float2*)(sX[b] + (row+8)*STRX + kst*16 + 2*tg + 8);
                    a[mb][0] = pack_h2(p0.x, p0.y);
                    a[mb][1] = pack_h2(p1.x, p1.y);
                    a[mb][2] = pack_h2(p2.x, p2.y);
                    a[mb][3] = pack_h2(p3.x, p3.y);
                }
#pragma unroll
                for (int nb = 0; nb < 8; ++nb) {
                    unsigned bb[2] = { sOM[(nb*8+gr)*STRO + kst*8 + tg],
                                       sOM[(nb*8+gr)*STRO + kst*8 + 4 + tg] };
                    mmaf16(cq[0][nb], a[0], bb);
                    mmaf16(cq[1][nb], a[1], bb);
                }
            }
            // q' = h * exp: m-pairs -> qP[s][m/2]
#pragma unroll
            for (int mb = 0; mb < 2; ++mb) {
                int row = w*32 + mb*16 + gr;
                float h0 = hr[row], h8 = hr[row+8];
#pragma unroll
                for (int nb = 0; nb < 8; ++nb) {
                    int mp = nb*4 + tg;
                    qP[row*STRO + mp]     = pack_h2(h0*__expf(cq[mb][nb][0]), h0*__expf(cq[mb][nb][1]));
                    qP[(row+8)*STRO + mp] = pack_h2(h8*__expf(cq[mb][nb][2]), h8*__expf(cq[mb][nb][3]));
                }
            }
        }
        __syncthreads();

        // GEMM3: D[s][c=72] = q' x buf1 over m=64 (4 k16 steps, B from regs)
        float dq[2][9][4];
#pragma unroll
        for (int mb = 0; mb < 2; ++mb)
#pragma unroll
            for (int nb = 0; nb < 9; ++nb)
#pragma unroll
                for (int q = 0; q < 4; ++q) dq[mb][nb][q] = 0.f;

#pragma unroll
        for (int kst = 0; kst < 4; ++kst) {
            unsigned a[2][4];
#pragma unroll
            for (int mb = 0; mb < 2; ++mb) {
                int row = w*32 + mb*16 + gr;
                a[mb][0] = qP[row*STRO     + kst*8 + tg];
                a[mb][1] = qP[(row+8)*STRO + kst*8 + tg];
                a[mb][2] = qP[row*STRO     + kst*8 + 4 + tg];
                a[mb][3] = qP[(row+8)*STRO + kst*8 + 4 + tg];
            }
#pragma unroll
            for (int nb = 0; nb < 9; ++nb) {
                mmaf16(dq[0][nb], a[0], b1r[kst][nb]);
                mmaf16(dq[1][nb], a[1], b1r[kst][nb]);
            }
        }

        // divide by denominator (c=64: nb=8 subcol 0), stage into X buffer b
        float* stg = sX[b];
#pragma unroll
        for (int mb = 0; mb < 2; ++mb) {
            int row = w*32 + mb*16 + gr;
            float den0 = __shfl_sync(0xffffffffu, dq[mb][8][0], lane & 28);
            float den8 = __shfl_sync(0xffffffffu, dq[mb][8][2], lane & 28);
            float inv0 = 1.0f / den0, inv8 = 1.0f / den8;
#pragma unroll
            for (int nb = 0; nb < 8; ++nb) {
                int col = nb*8 + 2*tg;
                stg[row*STRX + col]       = dq[mb][nb][0]*inv0;
                stg[row*STRX + col + 1]   = dq[mb][nb][1]*inv0;
                stg[(row+8)*STRX + col]   = dq[mb][nb][2]*inv8;
                stg[(row+8)*STRX + col+1] = dq[mb][nb][3]*inv8;
            }
        }
        __syncthreads();

        // coalesced store 128x64
        float* ob = Out + base0 + (size_t)t*TS*D_;
        for (int i = tid; i < 2048; i += 128) {
            int r = i >> 4, c4 = i & 15;
            float4 v = *(float4*)&stg[r*STRX + 4*c4];
            ((float4*)(ob + (size_t)r*D_))[c4] = v;
        }
        __syncthreads();   // stg reused as cp.async dst two tiles later
    }
}

extern "C" void kernel_launch(void* const* d_in, const int* in_sizes, int n_in,
                              void* d_out, int out_size)
{
    const float* Q  = (const float*)d_in[0];
    const float* K  = (const float*)d_in[1];
    const float* V  = (const float*)d_in[2];
    const float* Om = (const float*)d_in[3];
    float* out = (float*)d_out;
    (void)in_sizes; (void)n_in; (void)out_size;

    const int SMEM_K = PK_WORDS * 4;
    const int SMEM_Q = PQ_WORDS * 4;
    cudaFuncSetAttribute(pk_kernel, cudaFuncAttributeMaxDynamicSharedMemorySize, SMEM_K);
    cudaFuncSetAttribute(pq_kernel, cudaFuncAttributeMaxDynamicSharedMemorySize, SMEM_Q);

    zero_buf1_kernel<<<(BH_*M_*C_ + 255)/256, 256>>>();
    pk_kernel<<<dim3(BH_, S_/(TS*NT)), 128, SMEM_K>>>(K, V, Om);
    pq_kernel<<<dim3(BH_, S_/(TS*NT)), 128, SMEM_Q>>>(Q, out, Om);
}

// round 14
// speedup vs baseline: 1.4119x; 1.1048x over previous
#include <cuda_runtime.h>
#include <cuda_fp16.h>

// Fixed shapes
#define BH_ 64
#define S_  8192
#define D_  64
#define M_  64
#define C_  65
#define TS  128
#define NT  8      // tiles per CTA

#define LOG2E 1.4426950408889634f

__device__ float g_buf1[BH_*M_*C_];

__global__ void zero_buf1_kernel() {
    int i = blockIdx.x*blockDim.x + threadIdx.x;
    if (i < BH_*M_*C_) g_buf1[i] = 0.0f;
}

__device__ __forceinline__ unsigned pack_h2(float lo, float hi) {
    __half2 h = __floats2half2_rn(lo, hi);   // x = lo, y = hi
    return *reinterpret_cast<unsigned*>(&h);
}
__device__ __forceinline__ unsigned smem_u32(const void* p) {
    unsigned a;
    asm("{ .reg .u64 t; cvta.to.shared.u64 t, %1; cvt.u32.u64 %0, t; }" : "=r"(a) : "l"(p));
    return a;
}
__device__ __forceinline__ void cp16(unsigned saddr, const float* g) {
    asm volatile("cp.async.cg.shared.global [%0], [%1], 16;"
                 :: "r"(saddr), "l"(__cvta_generic_to_global(g)));
}
#define CP_COMMIT() asm volatile("cp.async.commit_group;")
#define CP_WAIT1()  asm volatile("cp.async.wait_group 1;")
#define CP_WAIT0()  asm volatile("cp.async.wait_group 0;")

// m16n8k16 fp16 MMA, fp32 accumulate, D += A*B
__device__ __forceinline__ void mmaf16(float* c, const unsigned* a, const unsigned* b) {
    asm volatile("mma.sync.aligned.m16n8k16.row.col.f32.f16.f16.f32 "
        "{%0,%1,%2,%3}, {%4,%5,%6,%7}, {%8,%9}, {%0,%1,%2,%3};"
        : "+f"(c[0]), "+f"(c[1]), "+f"(c[2]), "+f"(c[3])
        : "r"(a[0]), "r"(a[1]), "r"(a[2]), "r"(a[3]), "r"(b[0]), "r"(b[1]));
}

// Strides (32-bit words)
#define STRX 72   // raw fp32 tiles (K/V/Q)
#define STRO 36   // half2-packed over K-dim: sOM, qP, sB1
#define STRT 68   // half2-packed over s: kT, vT

// Phase K word offsets
#define KOF_OM 0u
#define KOF_X0 2432u
#define KOF_X1 (KOF_X0 + 128u*STRX)
#define KOF_V0 (KOF_X1 + 128u*STRX)
#define KOF_V1 (KOF_V0 + 128u*STRX)
#define KOF_KT (KOF_V1 + 128u*STRX)          // [64][68]
#define KOF_VT (KOF_KT + 64u*STRT)           // [64][68]
#define PK_WORDS (KOF_VT + 64u*STRT)         // 192000 B (1 CTA/SM)

// Phase Q word offsets (112 KB -> 2 CTAs/SM)
#define QOF_OM 0u
#define QOF_X0 2432u
#define QOF_X1 (QOF_X0 + 128u*STRX)
#define QOF_QP (QOF_X1 + 128u*STRX)          // [128][36]
#define QOF_B1 (QOF_QP + 128u*STRO)          // [72][36]
#define PQ_WORDS (QOF_B1 + 72u*STRO)

// One 128x64 fp32 tile, 16 cp.async per thread (128 threads, coalesced)
__device__ __forceinline__ void issue_tile(const float* g, unsigned sbase, int tid) {
#pragma unroll
    for (int j = 0; j < 16; ++j) {
        int l = j*128 + tid;
        int row = l >> 4, ch = l & 15;
        cp16(sbase + (unsigned)(row*STRX + ch*4)*4u, g + row*64 + ch*4);
    }
}

// omTh[m][j] = half2{ LOG2E*Om[2j][m], LOG2E*Om[2j+1][m] }  (pre-scaled for exp2)
__device__ __forceinline__ void setup_om(unsigned* sOM, const float* Og, int tid) {
    for (int i = tid; i < 2048; i += 128) {
        int m = i >> 5, j = i & 31;
        sOM[m*STRO + j] = pack_h2(LOG2E*Og[(2*j)*64 + m], LOG2E*Og[(2*j+1)*64 + m]);
    }
}

// ---------------------------------------------------------------------------
// Phase K: grid (64, 8), 128 threads, cp.async double-buffered.
// k'[s][m] = exp2( projL[s][m] + hv(s) ), hv = -0.5*ss*LOG2E - 3  (h = e^{-ss/2}/8)
// 2 syncs per tile; h exchanged by warp shuffle.
// ---------------------------------------------------------------------------
__global__ void __launch_bounds__(128)
pk_kernel(const float* __restrict__ Kg, const float* __restrict__ Vg,
          const float* __restrict__ Og)
{
    extern __shared__ unsigned sm[];
    unsigned* sOM = sm + KOF_OM;
    float*    sX[2] = { (float*)(sm + KOF_X0), (float*)(sm + KOF_X1) };
    float*    sV[2] = { (float*)(sm + KOF_V0), (float*)(sm + KOF_V1) };
    unsigned* kT = sm + KOF_KT;
    unsigned* vT = sm + KOF_VT;
    const unsigned xb[2] = { smem_u32(sm + KOF_X0), smem_u32(sm + KOF_X1) };
    const unsigned vb[2] = { smem_u32(sm + KOF_V0), smem_u32(sm + KOF_V1) };

    const int tid = threadIdx.x, w = tid >> 5, lane = tid & 31;
    const int gr = lane >> 2, tg = lane & 3;
    const int bh = blockIdx.x, sp = blockIdx.y;

    setup_om(sOM, Og, tid);

    float acc[9][4];
#pragma unroll
    for (int nb = 0; nb < 9; ++nb)
#pragma unroll
        for (int q = 0; q < 4; ++q) acc[nb][q] = 0.f;

    // Constant B-fragment for the [1|0..0] block (c=64..71)
    const unsigned bcn = (gr == 0) ? 0x3C003C00u : 0u;

    const size_t base0 = ((size_t)bh*S_ + (size_t)(sp*NT)*TS) * D_;
    issue_tile(Kg + base0, xb[0], tid);
    issue_tile(Vg + base0, vb[0], tid);
    CP_COMMIT();

    __syncthreads();  // sOM visible block-wide

    // Hoist omega A-fragments (loop-invariant): omr[kst][mb][q], 64 regs
    unsigned omr[4][4][4];
#pragma unroll
    for (int kst = 0; kst < 4; ++kst)
#pragma unroll
        for (int mb = 0; mb < 4; ++mb) {
            omr[kst][mb][0] = sOM[(mb*16+gr)*STRO   + kst*8 + tg];
            omr[kst][mb][1] = sOM[(mb*16+gr+8)*STRO + kst*8 + tg];
            omr[kst][mb][2] = sOM[(mb*16+gr)*STRO   + kst*8 + 4 + tg];
            omr[kst][mb][3] = sOM[(mb*16+gr+8)*STRO + kst*8 + 4 + tg];
        }

    for (int t = 0; t < NT; ++t) {
        const int b = t & 1;
        if (t + 1 < NT) {
            const size_t noff = base0 + (size_t)(t+1)*TS*D_;
            issue_tile(Kg + noff, xb[b^1], tid);
            issue_tile(Vg + noff, vb[b^1], tid);
            CP_COMMIT();
            CP_WAIT1();
        } else {
            CP_WAIT0();
        }
        __syncthreads();   // X/V(t) visible; GEMM2(t-1) done (kT/vT/sX/sV free)

        // hv for own row (kept in registers, exchanged by shuffle later)
        float hv;
        {
            const float4* rp = (const float4*)(sX[b] + tid*STRX);
            float ss = 0.f;
#pragma unroll
            for (int j = 0; j < 16; ++j) {
                float4 x = rp[j];
                ss += x.x*x.x + x.y*x.y + x.z*x.z + x.w*x.w;
            }
            hv = fmaf(ss, -0.5f*LOG2E, -3.0f);
        }
        // V^T 16-bit scatter from raw V
        {
            const float4* vp = (const float4*)(sV[b] + tid*STRX);
            __half* vh = (__half*)vT;
#pragma unroll
            for (int j = 0; j < 16; ++j) {
                float4 v = vp[j];
                vh[(4*j+0)*(2*STRT) + tid] = __float2half_rn(v.x);
                vh[(4*j+1)*(2*STRT) + tid] = __float2half_rn(v.y);
                vh[(4*j+2)*(2*STRT) + tid] = __float2half_rn(v.z);
                vh[(4*j+3)*(2*STRT) + tid] = __float2half_rn(v.w);
            }
        }

        // GEMM1^T: projL[m=64][s=128]; warp w owns s-cols 32w..+31
        float c1[4][4][4];
#pragma unroll
        for (int mb = 0; mb < 4; ++mb)
#pragma unroll
            for (int nb = 0; nb < 4; ++nb)
#pragma unroll
                for (int q = 0; q < 4; ++q) c1[mb][nb][q] = 0.f;

#pragma unroll
        for (int kst = 0; kst < 4; ++kst) {
#pragma unroll
            for (int nb = 0; nb < 4; ++nb) {
                int s = w*32 + nb*8 + gr;
                float2 x0 = *(const float2*)(sX[b] + s*STRX + kst*16 + 2*tg);
                float2 x1 = *(const float2*)(sX[b] + s*STRX + kst*16 + 2*tg + 8);
                unsigned bb[2] = { pack_h2(x0.x, x0.y), pack_h2(x1.x, x1.y) };
#pragma unroll
                for (int mb = 0; mb < 4; ++mb) mmaf16(c1[mb][nb], omr[kst][mb], bb);
            }
        }
        // k' = exp2(projL + hv): s-pairs -> kT[m][s/2]
#pragma unroll
        for (int nb = 0; nb < 4; ++nb) {
            int l0 = nb*8 + 2*tg;
            float hv0 = __shfl_sync(0xffffffffu, hv, l0);
            float hv1 = __shfl_sync(0xffffffffu, hv, l0 + 1);
            int spx = w*16 + nb*4 + tg;
#pragma unroll
            for (int mb = 0; mb < 4; ++mb) {
                int m = mb*16 + gr;
                kT[m*STRT + spx]     = pack_h2(exp2f(c1[mb][nb][0] + hv0), exp2f(c1[mb][nb][1] + hv1));
                kT[(m+8)*STRT + spx] = pack_h2(exp2f(c1[mb][nb][2] + hv0), exp2f(c1[mb][nb][3] + hv1));
            }
        }
        __syncthreads();   // kT/vT complete block-wide

        // GEMM2: acc[m16 of warp][c=72] += k'^T x V over s (8 k16 steps)
#pragma unroll
        for (int kst = 0; kst < 8; ++kst) {
            unsigned a[4];
            a[0] = kT[(w*16+gr)*STRT   + kst*8 + tg];
            a[1] = kT[(w*16+gr+8)*STRT + kst*8 + tg];
            a[2] = kT[(w*16+gr)*STRT   + kst*8 + 4 + tg];
            a[3] = kT[(w*16+gr+8)*STRT + kst*8 + 4 + tg];
#pragma unroll
            for (int nb = 0; nb < 8; ++nb) {
                unsigned bb[2] = { vT[(nb*8+gr)*STRT + kst*8 + tg],
                                   vT[(nb*8+gr)*STRT + kst*8 + 4 + tg] };
                mmaf16(acc[nb], a, bb);
            }
            { unsigned bc[2] = { bcn, bcn }; mmaf16(acc[8], a, bc); }
        }
        // loop-top sync separates GEMM2 reads from next tile's writes
    }

    // Fold into global buf1
    float* b1 = g_buf1 + (size_t)bh*(M_*C_);
    const int m = w*16 + gr;
#pragma unroll
    for (int nb = 0; nb < 9; ++nb) {
        int col = nb*8 + 2*tg;
        if (col < C_) {
            atomicAdd(&b1[m*C_ + col],     acc[nb][0]);
            atomicAdd(&b1[(m+8)*C_ + col], acc[nb][2]);
        }
        if (col + 1 < C_) {
            atomicAdd(&b1[m*C_ + col + 1],     acc[nb][1]);
            atomicAdd(&b1[(m+8)*C_ + col + 1], acc[nb][3]);
        }
    }
}

// ---------------------------------------------------------------------------
// Phase Q: grid (64, 8), 128 threads, 2 CTAs/SM.
// q' per-row scale cancels in num/den -> no h(s) at all: q' = exp2(projL).
// ---------------------------------------------------------------------------
__global__ void __launch_bounds__(128)
pq_kernel(const float* __restrict__ Qg, float* __restrict__ Out,
          const float* __restrict__ Og)
{
    extern __shared__ unsigned sm[];
    unsigned* sOM = sm + QOF_OM;
    float*    sX[2] = { (float*)(sm + QOF_X0), (float*)(sm + QOF_X1) };
    unsigned* qP = sm + QOF_QP;
    unsigned* sB1 = sm + QOF_B1;
    const unsigned xb[2] = { smem_u32(sm + QOF_X0), smem_u32(sm + QOF_X1) };

    const int tid = threadIdx.x, w = tid >> 5, lane = tid & 31;
    const int gr = lane >> 2, tg = lane & 3;
    const int bh = blockIdx.x, sp = blockIdx.y;

    setup_om(sOM, Og, tid);
    // B1h[c][j] = half2{ buf1[2j][c], buf1[2j+1][c] }; c>=65 zero
    const float* b1g = g_buf1 + (size_t)bh*(M_*C_);
    for (int i = tid; i < 72*32; i += 128) {
        int c = i >> 5, j = i & 31;
        unsigned v = 0u;
        if (c < C_) v = pack_h2(b1g[(2*j)*C_ + c], b1g[(2*j+1)*C_ + c]);
        sB1[c*STRO + j] = v;
    }

    const size_t base0 = ((size_t)bh*S_ + (size_t)(sp*NT)*TS) * D_;
    issue_tile(Qg + base0, xb[0], tid);
    CP_COMMIT();

    __syncthreads();  // sB1 visible block-wide

    // Hoist buf1 B-fragments (loop-invariant): b1r[kst][nb][2], 72 regs
    unsigned b1r[4][9][2];
#pragma unroll
    for (int kst = 0; kst < 4; ++kst)
#pragma unroll
        for (int nb = 0; nb < 9; ++nb) {
            b1r[kst][nb][0] = sB1[(nb*8+gr)*STRO + kst*8 + tg];
            b1r[kst][nb][1] = sB1[(nb*8+gr)*STRO + kst*8 + 4 + tg];
        }

    for (int t = 0; t < NT; ++t) {
        const int b = t & 1;
        if (t + 1 < NT) {
            issue_tile(Qg + base0 + (size_t)(t+1)*TS*D_, xb[b^1], tid);
            CP_COMMIT();
            CP_WAIT1();
        } else {
            CP_WAIT0();
        }
        __syncthreads();   // X(t) visible

        // GEMM1: q'[s=128][m=64]; warp w rows 32w..+31
        {
            float cq[2][8][4];
#pragma unroll
            for (int mb = 0; mb < 2; ++mb)
#pragma unroll
                for (int nb = 0; nb < 8; ++nb)
#pragma unroll
                    for (int q = 0; q < 4; ++q) cq[mb][nb][q] = 0.f;

#pragma unroll
            for (int kst = 0; kst < 4; ++kst) {
                unsigned a[2][4];
#pragma unroll
                for (int mb = 0; mb < 2; ++mb) {
                    int row = w*32 + mb*16 + gr;
                    float2 p0 = *(const float2*)(sX[b] + row*STRX     + kst*16 + 2*tg);
                    float2 p1 = *(const float2*)(sX[b] + (row+8)*STRX + kst*16 + 2*tg);
                    float2 p2 = *(const float2*)(sX[b] + row*STRX     + kst*16 + 2*tg + 8);
                    float2 p3 = *(const float2*)(sX[b] + (row+8)*STRX + kst*16 + 2*tg + 8);
                    a[mb][0] = pack_h2(p0.x, p0.y);
                    a[mb][1] = pack_h2(p1.x, p1.y);
                    a[mb][2] = pack_h2(p2.x, p2.y);
                    a[mb][3] = pack_h2(p3.x, p3.y);
                }
#pragma unroll
                for (int nb = 0; nb < 8; ++nb) {
                    unsigned bb[2] = { sOM[(nb*8+gr)*STRO + kst*8 + tg],
                                       sOM[(nb*8+gr)*STRO + kst*8 + 4 + tg] };
                    mmaf16(cq[0][nb], a[0], bb);
                    mmaf16(cq[1][nb], a[1], bb);
                }
            }
            // q' = exp2(projL): m-pairs -> qP[s][m/2]
#pragma unroll
            for (int mb = 0; mb < 2; ++mb) {
                int row = w*32 + mb*16 + gr;
#pragma unroll
                for (int nb = 0; nb < 8; ++nb) {
                    int mp = nb*4 + tg;
                    qP[row*STRO + mp]     = pack_h2(exp2f(cq[mb][nb][0]), exp2f(cq[mb][nb][1]));
                    qP[(row+8)*STRO + mp] = pack_h2(exp2f(cq[mb][nb][2]), exp2f(cq[mb][nb][3]));
                }
            }
        }
        __syncthreads();   // qP complete; sX[b] reads all done

        // GEMM3: D[s][c=72] = q' x buf1 over m=64 (4 k16 steps, B from regs)
        float dq[2][9][4];
#pragma unroll
        for (int mb = 0; mb < 2; ++mb)
#pragma unroll
            for (int nb = 0; nb < 9; ++nb)
#pragma unroll
                for (int q = 0; q < 4; ++q) dq[mb][nb][q] = 0.f;

#pragma unroll
        for (int kst = 0; kst < 4; ++kst) {
            unsigned a[2][4];
#pragma unroll
            for (int mb = 0; mb < 2; ++mb) {
                int row = w*32 + mb*16 + gr;
                a[mb][0] = qP[row*STRO     + kst*8 + tg];
                a[mb][1] = qP[(row+8)*STRO + kst*8 + tg];
                a[mb][2] = qP[row*STRO     + kst*8 + 4 + tg];
                a[mb][3] = qP[(row+8)*STRO + kst*8 + 4 + tg];
            }
#pragma unroll
            for (int nb = 0; nb < 9; ++nb) {
                mmaf16(dq[0][nb], a[0], b1r[kst][nb]);
                mmaf16(dq[1][nb], a[1], b1r[kst][nb]);
            }
        }

        // divide by denominator (c=64: nb=8 subcol 0), stage into X buffer b
        float* stg = sX[b];
#pragma unroll
        for (int mb = 0; mb < 2; ++mb) {
            int row = w*32 + mb*16 + gr;
            float den0 = __shfl_sync(0xffffffffu, dq[mb][8][0], lane & 28);
            float den8 = __shfl_sync(0xffffffffu, dq[mb][8][2], lane & 28);
            float inv0 = 1.0f / den0, inv8 = 1.0f / den8;
#pragma unroll
            for (int nb = 0; nb < 8; ++nb) {
                int col = nb*8 + 2*tg;
                stg[row*STRX + col]       = dq[mb][nb][0]*inv0;
                stg[row*STRX + col + 1]   = dq[mb][nb][1]*inv0;
                stg[(row+8)*STRX + col]   = dq[mb][nb][2]*inv8;
                stg[(row+8)*STRX + col+1] = dq[mb][nb][3]*inv8;
            }
        }
        __syncthreads();   // staging complete

        // coalesced store 128x64
        float* ob = Out + base0 + (size_t)t*TS*D_;
        for (int i = tid; i < 2048; i += 128) {
            int r = i >> 4, c4 = i & 15;
            float4 v = *(float4*)&stg[r*STRX + 4*c4];
            ((float4*)(ob + (size_t)r*D_))[c4] = v;
        }
        __syncthreads();   // stg (= next cp.async dst) reads done before issue
    }
}

extern "C" void kernel_launch(void* const* d_in, const int* in_sizes, int n_in,
                              void* d_out, int out_size)
{
    const float* Q  = (const float*)d_in[0];
    const float* K  = (const float*)d_in[1];
    const float* V  = (const float*)d_in[2];
    const float* Om = (const float*)d_in[3];
    float* out = (float*)d_out;
    (void)in_sizes; (void)n_in; (void)out_size;

    const int SMEM_K = PK_WORDS * 4;
    const int SMEM_Q = PQ_WORDS * 4;
    cudaFuncSetAttribute(pk_kernel, cudaFuncAttributeMaxDynamicSharedMemorySize, SMEM_K);
    cudaFuncSetAttribute(pq_kernel, cudaFuncAttributeMaxDynamicSharedMemorySize, SMEM_Q);

    zero_buf1_kernel<<<(BH_*M_*C_ + 255)/256, 256>>>();
    pk_kernel<<<dim3(BH_, S_/(TS*NT)), 128, SMEM_K>>>(K, V, Om);
    pq_kernel<<<dim3(BH_, S_/(TS*NT)), 128, SMEM_Q>>>(Q, out, Om);
}